// round 15
// baseline (speedup 1.0000x reference)
#include <cuda_runtime.h>

// Problem constants
#define FD      1024          // feature dim
#define NB      128           // batch / steps
#define KD      4096          // 4 * FD (flattened conv reduction dim)
#define NSPLIT  16            // K-splits for the GEMM (R5 optimum)
#define KCHUNK  256           // KD / NSPLIT
#define GEMM_BLOCKS 256       // 16 n-tiles * 16 k-splits
#define NSRC    1535          // 511 conv + 512 short + 512 input source rows
#define CHUNKS  4             // chunks per scatter source row (strided dests)
#define CCHUNKS 4             // chunks per comp row (strided dests)
#define SCAT_BLOCKS (NSRC * CHUNKS)              // 6140
#define COMP_BLOCKS (NB * CCHUNKS)               // 512
#define COMP_BASE   (GEMM_BLOCKS + SCAT_BLOCKS)  // comp blocks scheduled LAST
#define TOTAL_BLOCKS (COMP_BASE + COMP_BLOCKS)   // 6908

// Packed fp32x2 helpers (Blackwell: dual-lane fp32 FMA, PTX-only)
#define PACK_F32X2(out, lo, hi) \
    asm("mov.b64 %0, {%1, %2};" : "=l"(out) : "f"(lo), "f"(hi))
#define UNPACK_F32X2(lo, hi, in) \
    asm("mov.b64 {%0, %1}, %2;" : "=f"(lo), "=f"(hi) : "l"(in))
#define FMA_F32X2(acc, a, b) \
    asm("fma.rn.f32x2 %0, %1, %2, %3;" : "=l"(acc) : "l"(a), "l"(b), "l"(acc))

// Split-K partial sums: [ksplit][s][1024]  (8 MB, fully rewritten each launch)
__device__ float g_part[NSPLIT * NB * FD];
// Cross-block gate state (BSS-zeroed at load; reset at end of every launch so
// graph replays start clean)
__device__ unsigned g_done;    // # GEMM blocks completed
__device__ unsigned g_taken;   // # comp blocks past the gate + done

// ---------------------------------------------------------------------------
// Single fused kernel — R13 champion with one change: the GEMM inner loop
// uses packed fma.rn.f32x2 (M-paired accumulators), halving fma-pipe issue
// cycles and therefore the GEMM wall time that interferes with the copy
// stream during wave 1. Per-lane arithmetic is bit-identical fp32 FMA.
//   blocks [0, 256)             : split-K GEMM partials  -> g_part, signal
//   blocks [256, 256+6140)      : source-centric scatter (strided chunks)
//   blocks [6396, 6908)         : gate on GEMM, reduce partials + bias,
//                                 scatter comp rows (strided chunks)
// ---------------------------------------------------------------------------
__global__ __launch_bounds__(256) void fused_kernel(
    const float* __restrict__ inp,   // inputs, viewed as (512, 1024)
    const float* __restrict__ mem,   // memory  (1024, 1024)
    const float* __restrict__ wk,    // kernel, viewed as (4096, 1024)
    const float* __restrict__ bias,  // (1024,)
    float* __restrict__ out)         // (128, 1024, 1024)
{
    if (blockIdx.x < GEMM_BLOCKS) {
        // -------- split-K GEMM:  partial[ks] = OLD[:, kchunk] @ Kflat[kchunk, ntile]
        __shared__ float As[16 * 128];   // [k][s]   (transposed A tile)
        __shared__ float Bs[16 * 64];    // [k][n]
        const int nt  = blockIdx.x & 15;        // n-tile (64 cols)
        const int ks  = blockIdx.x >> 4;        // k-split
        const int tid = threadIdx.x;
        const int tx  = tid & 15;               // 16 threads * 4 cols = 64
        const int ty  = tid >> 4;               // 16 threads * 8 rows = 128
        const float* A = mem + 512 * FD;        // OLD (128, 4096), contiguous

        // acc2[mp][n] holds the (m=2mp, m=2mp+1) pair for output column n
        unsigned long long acc2[4][4];
        #pragma unroll
        for (int mp = 0; mp < 4; ++mp)
            #pragma unroll
            for (int n = 0; n < 4; ++n) acc2[mp][n] = 0ULL;   // (0.0f, 0.0f)

        const int kc0 = ks * KCHUNK;
        for (int kt = 0; kt < 16; ++kt) {
            const int kb = kc0 + kt * 16;
            // load A tile (128 rows x 16 cols) transposed into As[k][s]
            #pragma unroll
            for (int i = 0; i < 2; ++i) {
                const int f  = tid + i * 256;       // 512 float4 total
                const int s  = f >> 2;
                const int c4 = (f & 3) * 4;
                const float4 v = *reinterpret_cast<const float4*>(A + (size_t)s * KD + kb + c4);
                As[(c4 + 0) * 128 + s] = v.x;
                As[(c4 + 1) * 128 + s] = v.y;
                As[(c4 + 2) * 128 + s] = v.z;
                As[(c4 + 3) * 128 + s] = v.w;
            }
            // load B tile (16 rows x 64 cols)
            {
                const int kk = tid >> 4;
                const int c4 = (tid & 15) * 4;
                *reinterpret_cast<float4*>(&Bs[kk * 64 + c4]) =
                    *reinterpret_cast<const float4*>(wk + (size_t)(kb + kk) * FD + nt * 64 + c4);
            }
            __syncthreads();
            #pragma unroll
            for (int k = 0; k < 16; ++k) {
                const float4 a0 = *reinterpret_cast<const float4*>(&As[k * 128 + ty * 8]);
                const float4 a1 = *reinterpret_cast<const float4*>(&As[k * 128 + ty * 8 + 4]);
                const float4 bv = *reinterpret_cast<const float4*>(&Bs[k * 64 + tx * 4]);
                // M-pairs come free from the float4 loads
                unsigned long long ap[4];
                PACK_F32X2(ap[0], a0.x, a0.y);
                PACK_F32X2(ap[1], a0.z, a0.w);
                PACK_F32X2(ap[2], a1.x, a1.y);
                PACK_F32X2(ap[3], a1.z, a1.w);
                // B values duplicated into both lanes (ALU pipe, overlaps fma)
                unsigned long long bb[4];
                PACK_F32X2(bb[0], bv.x, bv.x);
                PACK_F32X2(bb[1], bv.y, bv.y);
                PACK_F32X2(bb[2], bv.z, bv.z);
                PACK_F32X2(bb[3], bv.w, bv.w);
                #pragma unroll
                for (int mp = 0; mp < 4; ++mp) {
                    FMA_F32X2(acc2[mp][0], ap[mp], bb[0]);
                    FMA_F32X2(acc2[mp][1], ap[mp], bb[1]);
                    FMA_F32X2(acc2[mp][2], ap[mp], bb[2]);
                    FMA_F32X2(acc2[mp][3], ap[mp], bb[3]);
                }
            }
            __syncthreads();
        }
        #pragma unroll
        for (int mp = 0; mp < 4; ++mp) {
            float lo[4], hi[4];
            #pragma unroll
            for (int n = 0; n < 4; ++n) UNPACK_F32X2(lo[n], hi[n], acc2[mp][n]);
            const float4 rlo = make_float4(lo[0], lo[1], lo[2], lo[3]);
            const float4 rhi = make_float4(hi[0], hi[1], hi[2], hi[3]);
            *reinterpret_cast<float4*>(
                &g_part[(size_t)(ks * NB + ty * 8 + 2 * mp) * FD + nt * 64 + tx * 4]) = rlo;
            *reinterpret_cast<float4*>(
                &g_part[(size_t)(ks * NB + ty * 8 + 2 * mp + 1) * FD + nt * 64 + tx * 4]) = rhi;
        }
        // signal completion: cta-scope sync chains into tid0's gpu-scope release
        __syncthreads();
        if (threadIdx.x == 0) {
            __threadfence();
            atomicAdd(&g_done, 1u);
        }
    } else if (blockIdx.x < COMP_BASE) {
        // -------- source-centric scatter of all non-comp output rows
        const int id    = blockIdx.x - GEMM_BLOCKS;
        const int sid   = id >> 2;       // source row id
        const int chunk = id & 3;        // strided dest class: d = chunk + 4k
        const int t     = threadIdx.x;   // one float4 per thread (256 * 4 = 1024)

        const float* src;
        int nb, rbase, rstep;
        if (sid < 511) {
            // conv-memory row c = sid+1 -> out[b][c-1-b] for b in [0, min(c-1,127)]
            const int c = sid + 1;
            nb    = (c < 128) ? c : 128;
            rbase = c - 1;
            rstep = -1;
            src   = mem + (size_t)c * FD;
        } else if (sid < 1023) {
            // short-memory row h -> out[b][508+h-4b] for b in [0, h/4-1]
            const int h = sid - 511;
            nb    = h >> 2;
            rbase = 508 + h;
            rstep = -4;
            src   = mem + (size_t)(512 + h) * FD;
        } else {
            // input flat row x -> out[b][1020+x-4b] for b in [x/4, 127]
            const int x = sid - 1023;
            const int b0 = x >> 2;
            nb    = 128 - b0;
            rbase = 1020 + x;   // row = rbase + rstep*b
            rstep = -4;
            src   = inp + (size_t)x * FD;
        }
        const int bfirst = (sid >= 1023) ? ((sid - 1023) >> 2) : 0;
        if (chunk >= nb) return;

        const float4 v = *reinterpret_cast<const float4*>(src + t * 4);
        for (int d = chunk; d < nb; d += CHUNKS) {
            const int b   = bfirst + d;
            const int row = rbase + rstep * b;
            *reinterpret_cast<float4*>(out + ((size_t)b * FD + row) * FD + t * 4) = v;
        }
    } else {
        // -------- comp rows: gate on GEMM, reduce 16 partials + bias, scatter.
        // comp row j goes to out[b][511+j-b] for b in [j, 127]; with d = b-j the
        // dest row is simply 511-d.
        const int id    = blockIdx.x - COMP_BASE;
        const int j     = id >> 2;       // comp row 0..127
        const int chunk = id & 3;        // strided dest class: d = chunk + 4k
        const int t     = threadIdx.x;

        // Gate: wait until all 256 GEMM blocks have published g_part.
        // These blocks are scheduled many waves after the GEMM finishes, so in
        // practice the spin count is zero.
        if (threadIdx.x == 0) {
            while (atomicAdd(&g_done, 0u) < (unsigned)GEMM_BLOCKS) __nanosleep(64);
            __threadfence();   // acquire: order g_part reads after the flag
        }
        __syncthreads();

        const int n = NB - j;            // number of destinations for row j
        if (chunk < n) {
            float4 s = *reinterpret_cast<const float4*>(bias + t * 4);
            #pragma unroll
            for (int p = 0; p < NSPLIT; ++p) {
                const float4 v = *reinterpret_cast<const float4*>(
                    &g_part[(size_t)(p * NB + j) * FD + t * 4]);
                s.x += v.x; s.y += v.y; s.z += v.z; s.w += v.w;
            }
            for (int d = chunk; d < n; d += CCHUNKS) {
                const int b   = j + d;
                const int row = 511 - d;
                *reinterpret_cast<float4*>(out + ((size_t)b * FD + row) * FD + t * 4) = s;
            }
        }

        // Reset gate state for the next graph replay: the LAST comp block to
        // finish (all 512 have passed the gate by construction of g_taken)
        // zeroes both counters.
        __syncthreads();
        if (threadIdx.x == 0) {
            const unsigned tk = atomicAdd(&g_taken, 1u);
            if (tk == (unsigned)(COMP_BLOCKS - 1)) {
                g_done  = 0u;
                g_taken = 0u;
                __threadfence();
            }
        }
    }
}

extern "C" void kernel_launch(void* const* d_in, const int* in_sizes, int n_in,
                              void* d_out, int out_size)
{
    const float* inp  = (const float*)d_in[0];   // (128,4,1024) = (512,1024) flat
    const float* mem  = (const float*)d_in[1];   // (1024,1024)
    const float* wk   = (const float*)d_in[2];   // (4,1024,1024) = (4096,1024) flat
    const float* bias = (const float*)d_in[3];   // (1024,)
    float* out = (float*)d_out;                  // (128,1024,1024)

    fused_kernel<<<TOTAL_BLOCKS, 256>>>(inp, mem, wk, bias, out);
}